// round 15
// baseline (speedup 1.0000x reference)
#include <cuda_runtime.h>
#include <cuda_fp16.h>
#include <math.h>

// ---------------------------------------------------------------------------
// QuantumHybridCNN — fp16 tensor cores, round 15.
// K1: EXACT r8 kernel (proven 52.3us): conv1(HFMA2)+pool -> A1; conv2 = 3
//     shifted fp16 GEMMs, permuted M (in-thread pooling); STG.128 -> g_a2h;
//     blocks<64 also transpose fc_w -> g_fcwt.
// K2 (rewritten): fc GEMM M=128/block, NO smem staging — mma fragments LDG'd
//     directly from g_a2h (DRAM, sector-aligned) and g_fcwt (L2-resident).
//     No cp.async, no barriers in K-loop. Epilogue + fused quantum head.
// ---------------------------------------------------------------------------

#define B_MAX 32768

__device__ __align__(16) __half g_a2h[B_MAX * 1024];   // 64 MB
__device__ __align__(16) __half g_fcwt[64 * 1024];     // 128 KB

// ---- helpers ---------------------------------------------------------------
__device__ __forceinline__ void mma_f16(float* c, unsigned a0, unsigned a1,
                                        unsigned a2, unsigned a3,
                                        unsigned b0, unsigned b1) {
    asm volatile(
        "mma.sync.aligned.m16n8k16.row.col.f32.f16.f16.f32 "
        "{%0,%1,%2,%3},{%4,%5,%6,%7},{%8,%9},{%0,%1,%2,%3};\n"
        : "+f"(c[0]), "+f"(c[1]), "+f"(c[2]), "+f"(c[3])
        : "r"(a0), "r"(a1), "r"(a2), "r"(a3), "r"(b0), "r"(b1));
}
__device__ __forceinline__ unsigned ldh2(const __half* p) {      // smem
    return *(const unsigned*)p;
}
__device__ __forceinline__ unsigned ldh2g(const __half* p) {     // global
    return __ldg((const unsigned*)p);
}

// ===========================================================================
// K1. smem (bytes):
//   A1   half [32 r][34 pos][36]  @ 0       (78336)  pos 0/33 = zero guards
//   Wt   half [64 oc][104]        @ 78336   (13312)
//   Xh/SCR                        @ 91648   (10240)  Xh [32][68] h / 8x1280B
//   C1Wh @101888 (192)  C1Bh @102080 (64)  C2B @102144 (256) -> 102400 B
// ===========================================================================
#define K1_SMEM 102400
#define A1_RSTR 1224
#define A1_PSTR 36

__global__ __launch_bounds__(256, 2)
void k1_conv(const float* __restrict__ x,
             const float* __restrict__ c1w, const float* __restrict__ c1b,
             const float* __restrict__ c2w, const float* __restrict__ c2b,
             const float* __restrict__ fcw)
{
    extern __shared__ __align__(16) unsigned char smraw[];
    __half*  A1   = (__half*)smraw;
    __half*  Wt   = (__half*)(smraw + 78336);
    __half*  Xh   = (__half*)(smraw + 91648);
    __half2* C1Wh = (__half2*)(smraw + 101888);
    __half2* C1Bh = (__half2*)(smraw + 102080);
    float*   C2B  = (float*)(smraw + 102144);

    const int tid  = threadIdx.x;
    const int wid  = tid >> 5;
    const int lane = tid & 31;
    const int qrow = lane >> 2;
    const int qc   = lane & 3;
    const int row0 = blockIdx.x * 32;

    // ---- fc_w transpose (blocks 0..63) -------------------------------------
    if (blockIdx.x < 64) {
        int f = blockIdx.x * 1024 + tid * 4;
        float4 v = *(const float4*)(fcw + f);
        int k = f >> 6, j = f & 63;
        int oc = k >> 4, p = k & 15;
        __half* d = g_fcwt + p * 64 + oc;
        d[(j + 0) * 1024] = __float2half_rn(v.x);
        d[(j + 1) * 1024] = __float2half_rn(v.y);
        d[(j + 2) * 1024] = __float2half_rn(v.z);
        d[(j + 3) * 1024] = __float2half_rn(v.w);
    }

    // ---- staging -----------------------------------------------------------
    {
        const float4* xs = (const float4*)(x + row0 * 64);
        #pragma unroll
        for (int i = 0; i < 2; i++) {
            int idx = tid + i * 256;
            float4 f4 = xs[idx];
            int r = idx >> 4, c = (idx & 15) * 4;
            __half2* d = (__half2*)(Xh + r * 68 + c);
            d[0] = __floats2half2_rn(f4.x, f4.y);
            d[1] = __floats2half2_rn(f4.z, f4.w);
        }
    }
    if (tid < 48) {
        int icp = tid / 3, k = tid - icp * 3;
        C1Wh[icp * 3 + k] = __floats2half2_rn(c1w[(2 * icp) * 3 + k],
                                              c1w[(2 * icp + 1) * 3 + k]);
    }
    if (tid < 16) C1Bh[tid] = __floats2half2_rn(c1b[2 * tid], c1b[2 * tid + 1]);
    if (tid < 64) C2B[tid] = c2b[tid];
    for (int g = tid; g < 6144; g += 256) {
        int oc = g / 96, rem = g - oc * 96;
        int ic = rem / 3, s = rem - ic * 3;
        Wt[oc * 104 + s * 32 + ic] = __float2half_rn(c2w[g]);
    }
    #pragma unroll
    for (int i = 0; i < 4; i++) {
        int idx = tid + i * 256;
        int r = idx >> 5, rest = idx & 31;
        int pos = (rest & 16) ? 33 : 0;
        int icp = rest & 15;
        *(unsigned*)(A1 + r * A1_RSTR + pos * A1_PSTR + icp * 2) = 0u;
    }
    __syncthreads();

    // ---- conv1 (HFMA2) + relu + maxpool2 -> A1 -----------------------------
    {
        const int icp = tid >> 4, pp = tid & 15;
        const __half2 w0 = C1Wh[icp * 3 + 0];
        const __half2 w1 = C1Wh[icp * 3 + 1];
        const __half2 w2 = C1Wh[icp * 3 + 2];
        const __half2 bb = C1Bh[icp];
        const __half2 zz = __float2half2_rn(0.f);
        const __half  zh = __float2half(0.f);
        for (int r = 0; r < 32; r++) {
            const __half* xr = Xh + r * 68;
            #pragma unroll
            for (int g = 0; g < 2; g++) {
                int p = pp + g * 16;
                int l0 = 2 * p;
                __half xm = (p > 0)  ? xr[l0 - 1] : zh;
                __half xa = xr[l0];
                __half xb = xr[l0 + 1];
                __half xc = (p < 31) ? xr[l0 + 2] : zh;
                __half2 xm2 = __half2half2(xm), xa2 = __half2half2(xa);
                __half2 xb2 = __half2half2(xb), xc2 = __half2half2(xc);
                __half2 y0 = __hfma2(w2, xb2, __hfma2(w1, xa2, __hfma2(w0, xm2, bb)));
                __half2 y1 = __hfma2(w2, xc2, __hfma2(w1, xb2, __hfma2(w0, xa2, bb)));
                __half2 v  = __hmax2(__hmax2(y0, y1), zz);
                *(__half2*)(A1 + r * A1_RSTR + (1 + p) * A1_PSTR + 2 * icp) = v;
            }
        }
    }
    __syncthreads();

    // ---- conv2: 3 shifted GEMMs, permuted M, hoisted B-frags ---------------
    const int rg = wid >> 1;
    const int nh = wid & 1;

    unsigned bf[6][4][2];
    #pragma unroll
    for (int ks = 0; ks < 6; ks++) {
        const int s = ks >> 1, kh = (ks & 1) << 4;
        const __half* bp0 = Wt + (nh * 32 + qrow) * 104 + s * 32 + kh + 2 * qc;
        #pragma unroll
        for (int n = 0; n < 4; n++) {
            const __half* bp = bp0 + n * 832;
            bf[ks][n][0] = ldh2(bp);
            bf[ks][n][1] = ldh2(bp + 8);
        }
    }

    __half* scr = (__half*)(smraw + 91648) + wid * 640;

    #pragma unroll 1
    for (int rr = 0; rr < 8; rr++) {
        const int r = rg * 8 + rr;
        float c[2][4][4] = {};
        const __half* Abase = A1 + r * A1_RSTR + 2 * qc;

        #pragma unroll
        for (int ks = 0; ks < 6; ks++) {
            const int s = ks >> 1, kh = (ks & 1) << 4;
            unsigned a[2][4];
            #pragma unroll
            for (int t = 0; t < 2; t++) {
                const __half* app = Abase + (t * 16 + 2 * qrow + s) * A1_PSTR + kh;
                a[t][0] = ldh2(app);        a[t][1] = ldh2(app + A1_PSTR);
                a[t][2] = ldh2(app + 8);    a[t][3] = ldh2(app + A1_PSTR + 8);
            }
            #pragma unroll
            for (int n = 0; n < 4; n++) {
                mma_f16(c[0][n], a[0][0], a[0][1], a[0][2], a[0][3],
                        bf[ks][n][0], bf[ks][n][1]);
                mma_f16(c[1][n], a[1][0], a[1][1], a[1][2], a[1][3],
                        bf[ks][n][0], bf[ks][n][1]);
            }
        }

        // pool (in-thread) + bias + relu -> scr
        #pragma unroll
        for (int t = 0; t < 2; t++) {
            #pragma unroll
            for (int n = 0; n < 4; n++) {
                int jl = n * 8 + 2 * qc;
                float b0 = C2B[nh * 32 + jl], b1 = C2B[nh * 32 + jl + 1];
                float p0 = fmaxf(fmaxf(c[t][n][0], c[t][n][2]) + b0, 0.f);
                float p1 = fmaxf(fmaxf(c[t][n][1], c[t][n][3]) + b1, 0.f);
                *(__half2*)(scr + (t * 8 + qrow) * 40 + jl) =
                    __floats2half2_rn(p0, p1);
            }
        }
        __syncwarp();

        __half* dst = g_a2h + (size_t)(row0 + r) * 1024 + nh * 32;
        #pragma unroll
        for (int pass = 0; pass < 2; pass++) {
            int p  = (lane >> 2) + pass * 8;
            int ch = lane & 3;
            uint4 v = *(const uint4*)(scr + p * 40 + ch * 8);
            *(uint4*)(dst + p * 64 + ch * 8) = v;
        }
        __syncwarp();
    }
}

// ===========================================================================
// K2: fc GEMM M=128/block (grid 256), NO staging — direct-LDG fragments.
// warp (mg = wid&3, ng = wid>>2): m-rows [mg*32, mg*32+32), n-cols ng*32..+32.
// A-frags from g_a2h (a0+a2 cover one contiguous 32B sector per row — no
// over-fetch); B-frags from L2-resident g_fcwt. No barriers in K-loop.
// smem: Hf f32 [128][68] @0 (34816), QC @34816 (96), QS @34912 (96) -> 35008 B
// ===========================================================================
#define K2_SMEM 35008

__global__ __launch_bounds__(256, 2)
void k2_fc_head(const float* __restrict__ fcb,
                const float* __restrict__ prew, const float* __restrict__ preb,
                const float* __restrict__ qp,
                const float* __restrict__ postw, const float* __restrict__ postb,
                float* __restrict__ out)
{
    extern __shared__ __align__(16) unsigned char smraw[];
    float* Hf = (float*)smraw;
    float* QC = (float*)(smraw + 34816);
    float* QS = (float*)(smraw + 34912);

    const int tid  = threadIdx.x;
    const int wid  = tid >> 5;
    const int lane = tid & 31;
    const int qrow = lane >> 2;
    const int qc   = lane & 3;
    const int m0   = blockIdx.x * 128;
    const int mg   = wid & 3;
    const int ng   = wid >> 2;

    if (tid < 24) {
        float s, cc;
        sincosf(qp[tid] * 0.5f, &s, &cc);
        QC[tid] = cc; QS[tid] = s;
    }

    // ---- GEMM: direct-LDG fragments ----------------------------------------
    float c[2][4][4] = {};
    const __half* Abase = g_a2h + (size_t)(m0 + mg * 32 + qrow) * 1024 + 2 * qc;
    const __half* Bbase = g_fcwt + (size_t)(ng * 32 + qrow) * 1024 + 2 * qc;

    #pragma unroll 1
    for (int ch = 0; ch < 16; ch++) {
        const __half* Ac = Abase + ch * 64;
        const __half* Bc = Bbase + ch * 64;
        #pragma unroll
        for (int ks = 0; ks < 4; ks++) {
            unsigned a[2][4];
            #pragma unroll
            for (int t = 0; t < 2; t++) {
                const __half* ap = Ac + t * 16 * 1024 + ks * 16;
                a[t][0] = ldh2g(ap);            a[t][1] = ldh2g(ap + 8 * 1024);
                a[t][2] = ldh2g(ap + 8);        a[t][3] = ldh2g(ap + 8 * 1024 + 8);
            }
            #pragma unroll
            for (int n = 0; n < 4; n++) {
                const __half* bp = Bc + n * 8 * 1024 + ks * 16;
                unsigned b0 = ldh2g(bp), b1 = ldh2g(bp + 8);
                mma_f16(c[0][n], a[0][0], a[0][1], a[0][2], a[0][3], b0, b1);
                mma_f16(c[1][n], a[1][0], a[1][1], a[1][2], a[1][3], b0, b1);
            }
        }
    }

    // ---- bias + relu -> Hf -------------------------------------------------
    #pragma unroll
    for (int t = 0; t < 2; t++) {
        #pragma unroll
        for (int n = 0; n < 4; n++) {
            int j0 = ng * 32 + n * 8 + 2 * qc;
            int m  = mg * 32 + t * 16 + qrow;
            float b0 = __ldg(fcb + j0), b1 = __ldg(fcb + j0 + 1);
            *(float2*)(Hf + m * 68 + j0) =
                make_float2(fmaxf(c[t][n][0] + b0, 0.f), fmaxf(c[t][n][1] + b1, 0.f));
            *(float2*)(Hf + (m + 8) * 68 + j0) =
                make_float2(fmaxf(c[t][n][2] + b0, 0.f), fmaxf(c[t][n][3] + b1, 0.f));
        }
    }
    __syncthreads();

    // ---- quantum head: one thread per row (128 rows) -----------------------
    if (tid < 128) {
        const float* hrow = Hf + tid * 68;
        float4 acc = *(const float4*)preb;
        #pragma unroll
        for (int j4 = 0; j4 < 16; j4++) {
            float4 h4 = *(const float4*)(hrow + j4 * 4);
            float4 wa = __ldg((const float4*)prew + (j4 * 4 + 0));
            float4 wb = __ldg((const float4*)prew + (j4 * 4 + 1));
            float4 wc = __ldg((const float4*)prew + (j4 * 4 + 2));
            float4 wd = __ldg((const float4*)prew + (j4 * 4 + 3));
            acc.x = fmaf(h4.x, wa.x, acc.x); acc.y = fmaf(h4.x, wa.y, acc.y);
            acc.z = fmaf(h4.x, wa.z, acc.z); acc.w = fmaf(h4.x, wa.w, acc.w);
            acc.x = fmaf(h4.y, wb.x, acc.x); acc.y = fmaf(h4.y, wb.y, acc.y);
            acc.z = fmaf(h4.y, wb.z, acc.z); acc.w = fmaf(h4.y, wb.w, acc.w);
            acc.x = fmaf(h4.z, wc.x, acc.x); acc.y = fmaf(h4.z, wc.y, acc.y);
            acc.z = fmaf(h4.z, wc.z, acc.z); acc.w = fmaf(h4.z, wc.w, acc.w);
            acc.x = fmaf(h4.w, wd.x, acc.x); acc.y = fmaf(h4.w, wd.y, acc.y);
            acc.z = fmaf(h4.w, wd.z, acc.z); acc.w = fmaf(h4.w, wd.w, acc.w);
        }
        const float PI_2 = 1.57079632679489662f;
        float th[4] = { tanhf(acc.x) * PI_2, tanhf(acc.y) * PI_2,
                        tanhf(acc.z) * PI_2, tanhf(acc.w) * PI_2 };

        float st[16];
        #pragma unroll
        for (int i = 0; i < 16; i++) st[i] = 0.25f;

        #pragma unroll
        for (int w = 0; w < 4; w++) {
            float s, cc;
            sincosf(th[w] * 0.5f, &s, &cc);
            const int m = 8 >> w;
            #pragma unroll
            for (int i = 0; i < 16; i++) {
                if (!(i & m)) {
                    int j = i | m;
                    float aa = st[i], bb = st[j];
                    st[i] = cc * aa - s * bb;
                    st[j] = s * aa + cc * bb;
                }
            }
        }
        #pragma unroll
        for (int k = 0; k < 6; k++) {
            #pragma unroll
            for (int i = 0; i < 16; i++)
                if ((i & 8) && !(i & 4)) { float tv = st[i]; st[i] = st[i|4]; st[i|4] = tv; }
            #pragma unroll
            for (int i = 0; i < 16; i++)
                if ((i & 2) && !(i & 1)) { float tv = st[i]; st[i] = st[i|1]; st[i|1] = tv; }
            #pragma unroll
            for (int i = 0; i < 16; i++)
                if ((i & 4) && !(i & 2)) { float tv = st[i]; st[i] = st[i|2]; st[i|2] = tv; }
            #pragma unroll
            for (int w = 0; w < 4; w++) {
                float cc = QC[k * 4 + w], s = QS[k * 4 + w];
                const int m = 8 >> w;
                #pragma unroll
                for (int i = 0; i < 16; i++) {
                    if (!(i & m)) {
                        int j = i | m;
                        float aa = st[i], bb = st[j];
                        st[i] = cc * aa - s * bb;
                        st[j] = s * aa + cc * bb;
                    }
                }
            }
        }
        float z0 = 0.f, z1 = 0.f, z2 = 0.f, z3 = 0.f;
        #pragma unroll
        for (int i = 0; i < 16; i++) {
            float p = st[i] * st[i];
            z0 += (i & 8) ? -p : p;
            z1 += (i & 4) ? -p : p;
            z2 += (i & 2) ? -p : p;
            z3 += (i & 1) ? -p : p;
        }
        float tacc = __ldg(postb);
        tacc = fmaf(z0, __ldg(postw + 0), tacc);
        tacc = fmaf(z1, __ldg(postw + 1), tacc);
        tacc = fmaf(z2, __ldg(postw + 2), tacc);
        tacc = fmaf(z3, __ldg(postw + 3), tacc);
        out[m0 + tid] = 1.f / (1.f + expf(-tacc));
    }
}

// ===========================================================================
extern "C" void kernel_launch(void* const* d_in, const int* in_sizes, int n_in,
                              void* d_out, int out_size)
{
    const float* x     = (const float*)d_in[0];
    const float* c1w   = (const float*)d_in[1];
    const float* c1b   = (const float*)d_in[2];
    const float* c2w   = (const float*)d_in[3];
    const float* c2b   = (const float*)d_in[4];
    const float* fcw   = (const float*)d_in[5];
    const float* fcb   = (const float*)d_in[6];
    const float* prew  = (const float*)d_in[7];
    const float* preb  = (const float*)d_in[8];
    const float* qp    = (const float*)d_in[9];
    const float* postw = (const float*)d_in[10];
    const float* postb = (const float*)d_in[11];

    const int B = in_sizes[0] / 64;

    cudaFuncSetAttribute(k1_conv, cudaFuncAttributeMaxDynamicSharedMemorySize, K1_SMEM);
    cudaFuncSetAttribute(k2_fc_head, cudaFuncAttributeMaxDynamicSharedMemorySize, K2_SMEM);

    k1_conv<<<B / 32, 256, K1_SMEM>>>(x, c1w, c1b, c2w, c2b, fcw);
    k2_fc_head<<<B / 128, 256, K2_SMEM>>>(fcb, prew, preb, qp, postw, postb,
                                          (float*)d_out);
}

// round 16
// speedup vs baseline: 1.6024x; 1.6024x over previous
#include <cuda_runtime.h>
#include <cuda_fp16.h>
#include <math.h>

// ---------------------------------------------------------------------------
// QuantumHybridCNN — fp16 tensor cores, round 16.
// K1: EXACT r8 kernel (proven): conv1(HFMA2)+pool -> A1; conv2 = 3 shifted
//     fp16 GEMMs, permuted M (in-thread pooling); STG.128 -> g_a2h;
//     blocks<64 also transpose fc_w -> g_fcwt.
// K2: r8 geometry (M=128/block, grid 256, 2 blocks/SM) with 4-stage cp.async
//     pipeline and ONE sync per chunk (vs r8's 2-stage / 2 syncs).
//     Stage layout: [A 18432 B | W 9216 B] -> W offset = 9216 HALVES.
// ---------------------------------------------------------------------------

#define B_MAX 32768

__device__ __align__(16) __half g_a2h[B_MAX * 1024];   // 64 MB
__device__ __align__(16) __half g_fcwt[64 * 1024];     // 128 KB

// ---- helpers ---------------------------------------------------------------
__device__ __forceinline__ void mma_f16(float* c, unsigned a0, unsigned a1,
                                        unsigned a2, unsigned a3,
                                        unsigned b0, unsigned b1) {
    asm volatile(
        "mma.sync.aligned.m16n8k16.row.col.f32.f16.f16.f32 "
        "{%0,%1,%2,%3},{%4,%5,%6,%7},{%8,%9},{%0,%1,%2,%3};\n"
        : "+f"(c[0]), "+f"(c[1]), "+f"(c[2]), "+f"(c[3])
        : "r"(a0), "r"(a1), "r"(a2), "r"(a3), "r"(b0), "r"(b1));
}
__device__ __forceinline__ unsigned ldh2(const __half* p) {
    return *(const unsigned*)p;
}
__device__ __forceinline__ void cpa16(void* dst, const void* src) {
    unsigned d = (unsigned)__cvta_generic_to_shared(dst);
    asm volatile("cp.async.cg.shared.global [%0], [%1], 16;\n" :: "r"(d), "l"(src));
}

// ===========================================================================
// K1. smem (bytes):
//   A1   half [32 r][34 pos][36]  @ 0       (78336)  pos 0/33 = zero guards
//   Wt   half [64 oc][104]        @ 78336   (13312)
//   Xh/SCR                        @ 91648   (10240)  Xh [32][68] h / 8x1280B
//   C1Wh @101888 (192)  C1Bh @102080 (64)  C2B @102144 (256) -> 102400 B
// ===========================================================================
#define K1_SMEM 102400
#define A1_RSTR 1224
#define A1_PSTR 36

__global__ __launch_bounds__(256, 2)
void k1_conv(const float* __restrict__ x,
             const float* __restrict__ c1w, const float* __restrict__ c1b,
             const float* __restrict__ c2w, const float* __restrict__ c2b,
             const float* __restrict__ fcw)
{
    extern __shared__ __align__(16) unsigned char smraw[];
    __half*  A1   = (__half*)smraw;
    __half*  Wt   = (__half*)(smraw + 78336);
    __half*  Xh   = (__half*)(smraw + 91648);
    __half2* C1Wh = (__half2*)(smraw + 101888);
    __half2* C1Bh = (__half2*)(smraw + 102080);
    float*   C2B  = (float*)(smraw + 102144);

    const int tid  = threadIdx.x;
    const int wid  = tid >> 5;
    const int lane = tid & 31;
    const int qrow = lane >> 2;
    const int qc   = lane & 3;
    const int row0 = blockIdx.x * 32;

    // ---- fc_w transpose (blocks 0..63) -------------------------------------
    if (blockIdx.x < 64) {
        int f = blockIdx.x * 1024 + tid * 4;
        float4 v = *(const float4*)(fcw + f);
        int k = f >> 6, j = f & 63;
        int oc = k >> 4, p = k & 15;
        __half* d = g_fcwt + p * 64 + oc;
        d[(j + 0) * 1024] = __float2half_rn(v.x);
        d[(j + 1) * 1024] = __float2half_rn(v.y);
        d[(j + 2) * 1024] = __float2half_rn(v.z);
        d[(j + 3) * 1024] = __float2half_rn(v.w);
    }

    // ---- staging -----------------------------------------------------------
    {
        const float4* xs = (const float4*)(x + row0 * 64);
        #pragma unroll
        for (int i = 0; i < 2; i++) {
            int idx = tid + i * 256;
            float4 f4 = xs[idx];
            int r = idx >> 4, c = (idx & 15) * 4;
            __half2* d = (__half2*)(Xh + r * 68 + c);
            d[0] = __floats2half2_rn(f4.x, f4.y);
            d[1] = __floats2half2_rn(f4.z, f4.w);
        }
    }
    if (tid < 48) {
        int icp = tid / 3, k = tid - icp * 3;
        C1Wh[icp * 3 + k] = __floats2half2_rn(c1w[(2 * icp) * 3 + k],
                                              c1w[(2 * icp + 1) * 3 + k]);
    }
    if (tid < 16) C1Bh[tid] = __floats2half2_rn(c1b[2 * tid], c1b[2 * tid + 1]);
    if (tid < 64) C2B[tid] = c2b[tid];
    for (int g = tid; g < 6144; g += 256) {
        int oc = g / 96, rem = g - oc * 96;
        int ic = rem / 3, s = rem - ic * 3;
        Wt[oc * 104 + s * 32 + ic] = __float2half_rn(c2w[g]);
    }
    #pragma unroll
    for (int i = 0; i < 4; i++) {
        int idx = tid + i * 256;
        int r = idx >> 5, rest = idx & 31;
        int pos = (rest & 16) ? 33 : 0;
        int icp = rest & 15;
        *(unsigned*)(A1 + r * A1_RSTR + pos * A1_PSTR + icp * 2) = 0u;
    }
    __syncthreads();

    // ---- conv1 (HFMA2) + relu + maxpool2 -> A1 -----------------------------
    {
        const int icp = tid >> 4, pp = tid & 15;
        const __half2 w0 = C1Wh[icp * 3 + 0];
        const __half2 w1 = C1Wh[icp * 3 + 1];
        const __half2 w2 = C1Wh[icp * 3 + 2];
        const __half2 bb = C1Bh[icp];
        const __half2 zz = __float2half2_rn(0.f);
        const __half  zh = __float2half(0.f);
        for (int r = 0; r < 32; r++) {
            const __half* xr = Xh + r * 68;
            #pragma unroll
            for (int g = 0; g < 2; g++) {
                int p = pp + g * 16;
                int l0 = 2 * p;
                __half xm = (p > 0)  ? xr[l0 - 1] : zh;
                __half xa = xr[l0];
                __half xb = xr[l0 + 1];
                __half xc = (p < 31) ? xr[l0 + 2] : zh;
                __half2 xm2 = __half2half2(xm), xa2 = __half2half2(xa);
                __half2 xb2 = __half2half2(xb), xc2 = __half2half2(xc);
                __half2 y0 = __hfma2(w2, xb2, __hfma2(w1, xa2, __hfma2(w0, xm2, bb)));
                __half2 y1 = __hfma2(w2, xc2, __hfma2(w1, xb2, __hfma2(w0, xa2, bb)));
                __half2 v  = __hmax2(__hmax2(y0, y1), zz);
                *(__half2*)(A1 + r * A1_RSTR + (1 + p) * A1_PSTR + 2 * icp) = v;
            }
        }
    }
    __syncthreads();

    // ---- conv2: 3 shifted GEMMs, permuted M, hoisted B-frags ---------------
    const int rg = wid >> 1;
    const int nh = wid & 1;

    unsigned bf[6][4][2];
    #pragma unroll
    for (int ks = 0; ks < 6; ks++) {
        const int s = ks >> 1, kh = (ks & 1) << 4;
        const __half* bp0 = Wt + (nh * 32 + qrow) * 104 + s * 32 + kh + 2 * qc;
        #pragma unroll
        for (int n = 0; n < 4; n++) {
            const __half* bp = bp0 + n * 832;
            bf[ks][n][0] = ldh2(bp);
            bf[ks][n][1] = ldh2(bp + 8);
        }
    }

    __half* scr = (__half*)(smraw + 91648) + wid * 640;

    #pragma unroll 1
    for (int rr = 0; rr < 8; rr++) {
        const int r = rg * 8 + rr;
        float c[2][4][4] = {};
        const __half* Abase = A1 + r * A1_RSTR + 2 * qc;

        #pragma unroll
        for (int ks = 0; ks < 6; ks++) {
            const int s = ks >> 1, kh = (ks & 1) << 4;
            unsigned a[2][4];
            #pragma unroll
            for (int t = 0; t < 2; t++) {
                const __half* app = Abase + (t * 16 + 2 * qrow + s) * A1_PSTR + kh;
                a[t][0] = ldh2(app);        a[t][1] = ldh2(app + A1_PSTR);
                a[t][2] = ldh2(app + 8);    a[t][3] = ldh2(app + A1_PSTR + 8);
            }
            #pragma unroll
            for (int n = 0; n < 4; n++) {
                mma_f16(c[0][n], a[0][0], a[0][1], a[0][2], a[0][3],
                        bf[ks][n][0], bf[ks][n][1]);
                mma_f16(c[1][n], a[1][0], a[1][1], a[1][2], a[1][3],
                        bf[ks][n][0], bf[ks][n][1]);
            }
        }

        // pool (in-thread) + bias + relu -> scr
        #pragma unroll
        for (int t = 0; t < 2; t++) {
            #pragma unroll
            for (int n = 0; n < 4; n++) {
                int jl = n * 8 + 2 * qc;
                float b0 = C2B[nh * 32 + jl], b1 = C2B[nh * 32 + jl + 1];
                float p0 = fmaxf(fmaxf(c[t][n][0], c[t][n][2]) + b0, 0.f);
                float p1 = fmaxf(fmaxf(c[t][n][1], c[t][n][3]) + b1, 0.f);
                *(__half2*)(scr + (t * 8 + qrow) * 40 + jl) =
                    __floats2half2_rn(p0, p1);
            }
        }
        __syncwarp();

        __half* dst = g_a2h + (size_t)(row0 + r) * 1024 + nh * 32;
        #pragma unroll
        for (int pass = 0; pass < 2; pass++) {
            int p  = (lane >> 2) + pass * 8;
            int ch = lane & 3;
            uint4 v = *(const uint4*)(scr + p * 40 + ch * 8);
            *(uint4*)(dst + p * 64 + ch * 8) = v;
        }
        __syncwarp();
    }
}

// ===========================================================================
// K2: fc GEMM M=128/block (grid 256), 4-stage cp.async, ONE sync per chunk.
// smem (bytes): 4 stages x { A [128][72] (18432 B) + W [64][72] (9216 B) }
//   = 110592; QC @110592 (96), QS @110688 (96) -> 110784 B; 2 blocks/SM.
// Stage layout: W offset within stage = 9216 HALVES (= 18432 bytes).
// Hf f32 [128][68] (34816 B) overlays stages after GEMM.
// ===========================================================================
#define K2_SMEM 110784
#define K2_STG  27648    // bytes per stage
#define K2_WOFF 9216     // HALVES offset of W within a stage (= 18432 bytes)

__global__ __launch_bounds__(256, 2)
void k2_fc_head(const float* __restrict__ fcb,
                const float* __restrict__ prew, const float* __restrict__ preb,
                const float* __restrict__ qp,
                const float* __restrict__ postw, const float* __restrict__ postb,
                float* __restrict__ out)
{
    extern __shared__ __align__(16) unsigned char smraw[];
    float* QC = (float*)(smraw + 110592);
    float* QS = (float*)(smraw + 110688);
    float* Hf = (float*)smraw;

    const int tid  = threadIdx.x;
    const int wid  = tid >> 5;
    const int lane = tid & 31;
    const int qrow = lane >> 2;
    const int qc   = lane & 3;
    const int m0   = blockIdx.x * 128;
    const int mg   = wid & 3;
    const int ng   = wid >> 2;

    if (tid < 24) {
        float s, cc;
        sincosf(qp[tid] * 0.5f, &s, &cc);
        QC[tid] = cc; QS[tid] = s;
    }

    auto stage = [&](int st, int ch) {
        __half* dA = (__half*)(smraw + st * K2_STG);
        __half* dW = dA + K2_WOFF;
        const __half* srcA = g_a2h + (size_t)m0 * 1024 + ch * 64;
        const __half* srcW = g_fcwt + ch * 64;
        #pragma unroll
        for (int i = 0; i < 6; i++) {
            int idx = tid + i * 256;                  // [0,1536)
            if (idx < 1024) {
                int r = idx >> 3, kv = idx & 7;
                cpa16(dA + r * 72 + kv * 8, srcA + (size_t)r * 1024 + kv * 8);
            } else {
                int j = (idx - 1024) >> 3, kv = idx & 7;
                cpa16(dW + j * 72 + kv * 8, srcW + (size_t)j * 1024 + kv * 8);
            }
        }
        asm volatile("cp.async.commit_group;\n");
    };

    float c[2][4][4] = {};
    stage(0, 0); stage(1, 1); stage(2, 2);

    #pragma unroll 1
    for (int ch = 0; ch < 16; ch++) {
        if (ch < 14) asm volatile("cp.async.wait_group 2;\n");
        else         asm volatile("cp.async.wait_group 0;\n");
        __syncthreads();     // chunk ch visible; all warps past mma(ch-1)
        if (ch + 3 < 16) stage((ch + 3) & 3, ch + 3);
        else             asm volatile("cp.async.commit_group;\n");  // empty

        const __half* bufA = (__half*)(smraw + (ch & 3) * K2_STG);
        const __half* bufW = bufA + K2_WOFF;
        const __half* Ab = bufA + (mg * 32 + qrow) * 72 + 2 * qc;
        const __half* Bb = bufW + (ng * 32 + qrow) * 72 + 2 * qc;
        #pragma unroll
        for (int ks = 0; ks < 4; ks++) {
            unsigned a[2][4];
            #pragma unroll
            for (int t = 0; t < 2; t++) {
                const __half* ap = Ab + t * 1152 + ks * 16;
                a[t][0] = ldh2(ap);       a[t][1] = ldh2(ap + 576);
                a[t][2] = ldh2(ap + 8);   a[t][3] = ldh2(ap + 584);
            }
            #pragma unroll
            for (int n = 0; n < 4; n++) {
                const __half* bp = Bb + n * 576 + ks * 16;
                unsigned b0 = ldh2(bp), b1 = ldh2(bp + 8);
                mma_f16(c[0][n], a[0][0], a[0][1], a[0][2], a[0][3], b0, b1);
                mma_f16(c[1][n], a[1][0], a[1][1], a[1][2], a[1][3], b0, b1);
            }
        }
    }
    __syncthreads();    // all mma done; stage buffers dead -> Hf overlays

    // ---- bias + relu -> Hf -------------------------------------------------
    #pragma unroll
    for (int t = 0; t < 2; t++) {
        #pragma unroll
        for (int n = 0; n < 4; n++) {
            int j0 = ng * 32 + n * 8 + 2 * qc;
            int m  = mg * 32 + t * 16 + qrow;
            float b0 = __ldg(fcb + j0), b1 = __ldg(fcb + j0 + 1);
            *(float2*)(Hf + m * 68 + j0) =
                make_float2(fmaxf(c[t][n][0] + b0, 0.f), fmaxf(c[t][n][1] + b1, 0.f));
            *(float2*)(Hf + (m + 8) * 68 + j0) =
                make_float2(fmaxf(c[t][n][2] + b0, 0.f), fmaxf(c[t][n][3] + b1, 0.f));
        }
    }
    __syncthreads();

    // ---- quantum head: one thread per row (128 rows) -----------------------
    if (tid < 128) {
        const float* hrow = Hf + tid * 68;
        float4 acc = *(const float4*)preb;
        #pragma unroll
        for (int j4 = 0; j4 < 16; j4++) {
            float4 h4 = *(const float4*)(hrow + j4 * 4);
            float4 wa = __ldg((const float4*)prew + (j4 * 4 + 0));
            float4 wb = __ldg((const float4*)prew + (j4 * 4 + 1));
            float4 wc = __ldg((const float4*)prew + (j4 * 4 + 2));
            float4 wd = __ldg((const float4*)prew + (j4 * 4 + 3));
            acc.x = fmaf(h4.x, wa.x, acc.x); acc.y = fmaf(h4.x, wa.y, acc.y);
            acc.z = fmaf(h4.x, wa.z, acc.z); acc.w = fmaf(h4.x, wa.w, acc.w);
            acc.x = fmaf(h4.y, wb.x, acc.x); acc.y = fmaf(h4.y, wb.y, acc.y);
            acc.z = fmaf(h4.y, wb.z, acc.z); acc.w = fmaf(h4.y, wb.w, acc.w);
            acc.x = fmaf(h4.z, wc.x, acc.x); acc.y = fmaf(h4.z, wc.y, acc.y);
            acc.z = fmaf(h4.z, wc.z, acc.z); acc.w = fmaf(h4.z, wc.w, acc.w);
            acc.x = fmaf(h4.w, wd.x, acc.x); acc.y = fmaf(h4.w, wd.y, acc.y);
            acc.z = fmaf(h4.w, wd.z, acc.z); acc.w = fmaf(h4.w, wd.w, acc.w);
        }
        const float PI_2 = 1.57079632679489662f;
        float th[4] = { tanhf(acc.x) * PI_2, tanhf(acc.y) * PI_2,
                        tanhf(acc.z) * PI_2, tanhf(acc.w) * PI_2 };

        float st[16];
        #pragma unroll
        for (int i = 0; i < 16; i++) st[i] = 0.25f;

        #pragma unroll
        for (int w = 0; w < 4; w++) {
            float s, cc;
            sincosf(th[w] * 0.5f, &s, &cc);
            const int m = 8 >> w;
            #pragma unroll
            for (int i = 0; i < 16; i++) {
                if (!(i & m)) {
                    int j = i | m;
                    float aa = st[i], bb = st[j];
                    st[i] = cc * aa - s * bb;
                    st[j] = s * aa + cc * bb;
                }
            }
        }
        #pragma unroll
        for (int k = 0; k < 6; k++) {
            #pragma unroll
            for (int i = 0; i < 16; i++)
                if ((i & 8) && !(i & 4)) { float tv = st[i]; st[i] = st[i|4]; st[i|4] = tv; }
            #pragma unroll
            for (int i = 0; i < 16; i++)
                if ((i & 2) && !(i & 1)) { float tv = st[i]; st[i] = st[i|1]; st[i|1] = tv; }
            #pragma unroll
            for (int i = 0; i < 16; i++)
                if ((i & 4) && !(i & 2)) { float tv = st[i]; st[i] = st[i|2]; st[i|2] = tv; }
            #pragma unroll
            for (int w = 0; w < 4; w++) {
                float cc = QC[k * 4 + w], s = QS[k * 4 + w];
                const int m = 8 >> w;
                #pragma unroll
                for (int i = 0; i < 16; i++) {
                    if (!(i & m)) {
                        int j = i | m;
                        float aa = st[i], bb = st[j];
                        st[i] = cc * aa - s * bb;
                        st[j] = s * aa + cc * bb;
                    }
                }
            }
        }
        float z0 = 0.f, z1 = 0.f, z2 = 0.f, z3 = 0.f;
        #pragma unroll
        for (int i = 0; i < 16; i++) {
            float p = st[i] * st[i];
            z0 += (i & 8) ? -p : p;
            z1 += (i & 4) ? -p : p;
            z2 += (i & 2) ? -p : p;
            z3 += (i & 1) ? -p : p;
        }
        float tacc = __ldg(postb);
        tacc = fmaf(z0, __ldg(postw + 0), tacc);
        tacc = fmaf(z1, __ldg(postw + 1), tacc);
        tacc = fmaf(z2, __ldg(postw + 2), tacc);
        tacc = fmaf(z3, __ldg(postw + 3), tacc);
        out[m0 + tid] = 1.f / (1.f + expf(-tacc));
    }
}

// ===========================================================================
extern "C" void kernel_launch(void* const* d_in, const int* in_sizes, int n_in,
                              void* d_out, int out_size)
{
    const float* x     = (const float*)d_in[0];
    const float* c1w   = (const float*)d_in[1];
    const float* c1b   = (const float*)d_in[2];
    const float* c2w   = (const float*)d_in[3];
    const float* c2b   = (const float*)d_in[4];
    const float* fcw   = (const float*)d_in[5];
    const float* fcb   = (const float*)d_in[6];
    const float* prew  = (const float*)d_in[7];
    const float* preb  = (const float*)d_in[8];
    const float* qp    = (const float*)d_in[9];
    const float* postw = (const float*)d_in[10];
    const float* postb = (const float*)d_in[11];

    const int B = in_sizes[0] / 64;

    cudaFuncSetAttribute(k1_conv, cudaFuncAttributeMaxDynamicSharedMemorySize, K1_SMEM);
    cudaFuncSetAttribute(k2_fc_head, cudaFuncAttributeMaxDynamicSharedMemorySize, K2_SMEM);

    k1_conv<<<B / 32, 256, K1_SMEM>>>(x, c1w, c1b, c2w, c2b, fcw);
    k2_fc_head<<<B / 128, 256, K2_SMEM>>>(fcb, prew, preb, qp, postw, postb,
                                          (float*)d_out);
}

// round 17
// speedup vs baseline: 1.7031x; 1.0628x over previous
#include <cuda_runtime.h>
#include <cuda_fp16.h>
#include <math.h>

// ---------------------------------------------------------------------------
// QuantumHybridCNN — fp16 tensor cores, round 17.
// K1: r8 conv pipeline (proven); epilogue now writes CHUNK-MAJOR SWIZZLED
//     a2: g_a2c[p][b][64oc], 16B-unit u stored at u^(b&7). blocks<64 also
//     transpose fc_w -> g_fcw2[p][j][64oc] with u^(j&7) swizzle.
// K2: fc GEMM M=128/block; staging via cp.async.bulk (2 bulk ops/chunk,
//     mbarrier complete_tx) instead of 1536 LDGSTS/chunk. 4-stage pipeline.
//     Fragments LDS'd conflict-free thanks to baked-in XOR swizzle.
// ---------------------------------------------------------------------------

#define B_MAX 32768

__device__ __align__(128) __half g_a2c[16 * B_MAX * 64];  // 64 MB chunk-major
__device__ __align__(128) __half g_fcw2[16 * 64 * 64];    // 128 KB chunk-major

// ---- helpers ---------------------------------------------------------------
__device__ __forceinline__ void mma_f16(float* c, unsigned a0, unsigned a1,
                                        unsigned a2, unsigned a3,
                                        unsigned b0, unsigned b1) {
    asm volatile(
        "mma.sync.aligned.m16n8k16.row.col.f32.f16.f16.f32 "
        "{%0,%1,%2,%3},{%4,%5,%6,%7},{%8,%9},{%0,%1,%2,%3};\n"
        : "+f"(c[0]), "+f"(c[1]), "+f"(c[2]), "+f"(c[3])
        : "r"(a0), "r"(a1), "r"(a2), "r"(a3), "r"(b0), "r"(b1));
}
__device__ __forceinline__ unsigned ldh2(const __half* p) {
    return *(const unsigned*)p;
}
__device__ __forceinline__ unsigned s2u(const void* p) {
    return (unsigned)__cvta_generic_to_shared(p);
}
__device__ __forceinline__ void mbar_init(unsigned mbar, unsigned cnt) {
    asm volatile("mbarrier.init.shared.b64 [%0], %1;" :: "r"(mbar), "r"(cnt) : "memory");
}
__device__ __forceinline__ void mbar_expect_tx(unsigned mbar, unsigned bytes) {
    asm volatile("mbarrier.arrive.expect_tx.shared.b64 _, [%0], %1;"
                 :: "r"(mbar), "r"(bytes) : "memory");
}
__device__ __forceinline__ void bulk_g2s(unsigned dst, const void* src,
                                         unsigned bytes, unsigned mbar) {
    asm volatile(
        "cp.async.bulk.shared::cta.global.mbarrier::complete_tx::bytes "
        "[%0], [%1], %2, [%3];"
        :: "r"(dst), "l"(src), "r"(bytes), "r"(mbar) : "memory");
}
__device__ __forceinline__ void mbar_wait(unsigned mbar, unsigned parity) {
    asm volatile(
        "{\n\t.reg .pred P1;\n\t"
        "WAIT_LOOP_%=:\n\t"
        "mbarrier.try_wait.parity.acquire.cta.shared::cta.b64 P1, [%0], %1;\n\t"
        "@P1 bra.uni WAIT_DONE_%=;\n\t"
        "bra.uni WAIT_LOOP_%=;\n\t"
        "WAIT_DONE_%=:\n\t}"
        :: "r"(mbar), "r"(parity) : "memory");
}

// ===========================================================================
// K1. smem (bytes) — layout identical to r8:
//   A1   half [32 r][34 pos][36]  @ 0       (78336)
//   Wt   half [64 oc][104]        @ 78336   (13312)
//   Xh/SCR                        @ 91648   (10240)
//   C1Wh @101888 (192)  C1Bh @102080 (64)  C2B @102144 (256) -> 102400 B
// ===========================================================================
#define K1_SMEM 102400
#define A1_RSTR 1224
#define A1_PSTR 36

__global__ __launch_bounds__(256, 2)
void k1_conv(const float* __restrict__ x,
             const float* __restrict__ c1w, const float* __restrict__ c1b,
             const float* __restrict__ c2w, const float* __restrict__ c2b,
             const float* __restrict__ fcw)
{
    extern __shared__ __align__(16) unsigned char smraw[];
    __half*  A1   = (__half*)smraw;
    __half*  Wt   = (__half*)(smraw + 78336);
    __half*  Xh   = (__half*)(smraw + 91648);
    __half2* C1Wh = (__half2*)(smraw + 101888);
    __half2* C1Bh = (__half2*)(smraw + 102080);
    float*   C2B  = (float*)(smraw + 102144);

    const int tid  = threadIdx.x;
    const int wid  = tid >> 5;
    const int lane = tid & 31;
    const int qrow = lane >> 2;
    const int qc   = lane & 3;
    const int row0 = blockIdx.x * 32;

    // ---- fc_w transpose (blocks 0..63) -> g_fcw2[p][j][oc], swizzled ------
    if (blockIdx.x < 64) {
        int f = blockIdx.x * 1024 + tid * 4;
        float4 v = *(const float4*)(fcw + f);
        int k = f >> 6, j0 = f & 63;
        int oc = k >> 4, p = k & 15;
        int ub = oc >> 3, lo = oc & 7;
        float vv[4] = {v.x, v.y, v.z, v.w};
        #pragma unroll
        for (int e = 0; e < 4; e++) {
            int j = j0 + e;
            g_fcw2[p * 4096 + j * 64 + ((ub ^ (j & 7)) << 3) + lo] =
                __float2half_rn(vv[e]);
        }
    }

    // ---- staging -----------------------------------------------------------
    {
        const float4* xs = (const float4*)(x + row0 * 64);
        #pragma unroll
        for (int i = 0; i < 2; i++) {
            int idx = tid + i * 256;
            float4 f4 = xs[idx];
            int r = idx >> 4, c = (idx & 15) * 4;
            __half2* d = (__half2*)(Xh + r * 68 + c);
            d[0] = __floats2half2_rn(f4.x, f4.y);
            d[1] = __floats2half2_rn(f4.z, f4.w);
        }
    }
    if (tid < 48) {
        int icp = tid / 3, k = tid - icp * 3;
        C1Wh[icp * 3 + k] = __floats2half2_rn(c1w[(2 * icp) * 3 + k],
                                              c1w[(2 * icp + 1) * 3 + k]);
    }
    if (tid < 16) C1Bh[tid] = __floats2half2_rn(c1b[2 * tid], c1b[2 * tid + 1]);
    if (tid < 64) C2B[tid] = c2b[tid];
    for (int g = tid; g < 6144; g += 256) {
        int oc = g / 96, rem = g - oc * 96;
        int ic = rem / 3, s = rem - ic * 3;
        Wt[oc * 104 + s * 32 + ic] = __float2half_rn(c2w[g]);
    }
    #pragma unroll
    for (int i = 0; i < 4; i++) {
        int idx = tid + i * 256;
        int r = idx >> 5, rest = idx & 31;
        int pos = (rest & 16) ? 33 : 0;
        int icp = rest & 15;
        *(unsigned*)(A1 + r * A1_RSTR + pos * A1_PSTR + icp * 2) = 0u;
    }
    __syncthreads();

    // ---- conv1 (HFMA2) + relu + maxpool2 -> A1 -----------------------------
    {
        const int icp = tid >> 4, pp = tid & 15;
        const __half2 w0 = C1Wh[icp * 3 + 0];
        const __half2 w1 = C1Wh[icp * 3 + 1];
        const __half2 w2 = C1Wh[icp * 3 + 2];
        const __half2 bb = C1Bh[icp];
        const __half2 zz = __float2half2_rn(0.f);
        const __half  zh = __float2half(0.f);
        for (int r = 0; r < 32; r++) {
            const __half* xr = Xh + r * 68;
            #pragma unroll
            for (int g = 0; g < 2; g++) {
                int p = pp + g * 16;
                int l0 = 2 * p;
                __half xm = (p > 0)  ? xr[l0 - 1] : zh;
                __half xa = xr[l0];
                __half xb = xr[l0 + 1];
                __half xc = (p < 31) ? xr[l0 + 2] : zh;
                __half2 xm2 = __half2half2(xm), xa2 = __half2half2(xa);
                __half2 xb2 = __half2half2(xb), xc2 = __half2half2(xc);
                __half2 y0 = __hfma2(w2, xb2, __hfma2(w1, xa2, __hfma2(w0, xm2, bb)));
                __half2 y1 = __hfma2(w2, xc2, __hfma2(w1, xb2, __hfma2(w0, xa2, bb)));
                __half2 v  = __hmax2(__hmax2(y0, y1), zz);
                *(__half2*)(A1 + r * A1_RSTR + (1 + p) * A1_PSTR + 2 * icp) = v;
            }
        }
    }
    __syncthreads();

    // ---- conv2: 3 shifted GEMMs, permuted M, hoisted B-frags ---------------
    const int rg = wid >> 1;
    const int nh = wid & 1;

    unsigned bf[6][4][2];
    #pragma unroll
    for (int ks = 0; ks < 6; ks++) {
        const int s = ks >> 1, kh = (ks & 1) << 4;
        const __half* bp0 = Wt + (nh * 32 + qrow) * 104 + s * 32 + kh + 2 * qc;
        #pragma unroll
        for (int n = 0; n < 4; n++) {
            const __half* bp = bp0 + n * 832;
            bf[ks][n][0] = ldh2(bp);
            bf[ks][n][1] = ldh2(bp + 8);
        }
    }

    __half* scr = (__half*)(smraw + 91648) + wid * 640;

    #pragma unroll 1
    for (int rr = 0; rr < 8; rr++) {
        const int r = rg * 8 + rr;
        float c[2][4][4] = {};
        const __half* Abase = A1 + r * A1_RSTR + 2 * qc;

        #pragma unroll
        for (int ks = 0; ks < 6; ks++) {
            const int s = ks >> 1, kh = (ks & 1) << 4;
            unsigned a[2][4];
            #pragma unroll
            for (int t = 0; t < 2; t++) {
                const __half* app = Abase + (t * 16 + 2 * qrow + s) * A1_PSTR + kh;
                a[t][0] = ldh2(app);        a[t][1] = ldh2(app + A1_PSTR);
                a[t][2] = ldh2(app + 8);    a[t][3] = ldh2(app + A1_PSTR + 8);
            }
            #pragma unroll
            for (int n = 0; n < 4; n++) {
                mma_f16(c[0][n], a[0][0], a[0][1], a[0][2], a[0][3],
                        bf[ks][n][0], bf[ks][n][1]);
                mma_f16(c[1][n], a[1][0], a[1][1], a[1][2], a[1][3],
                        bf[ks][n][0], bf[ks][n][1]);
            }
        }

        // pool (in-thread) + bias + relu -> scr
        #pragma unroll
        for (int t = 0; t < 2; t++) {
            #pragma unroll
            for (int n = 0; n < 4; n++) {
                int jl = n * 8 + 2 * qc;
                float b0 = C2B[nh * 32 + jl], b1 = C2B[nh * 32 + jl + 1];
                float p0 = fmaxf(fmaxf(c[t][n][0], c[t][n][2]) + b0, 0.f);
                float p1 = fmaxf(fmaxf(c[t][n][1], c[t][n][3]) + b1, 0.f);
                *(__half2*)(scr + (t * 8 + qrow) * 40 + jl) =
                    __floats2half2_rn(p0, p1);
            }
        }
        __syncwarp();

        // copy scratch -> g_a2c chunk-major, XOR-swizzled units
        {
            const int b  = row0 + r;
            const int sw = b & 7;
            __half* dstb = g_a2c + (size_t)b * 64;
            #pragma unroll
            for (int pass = 0; pass < 2; pass++) {
                int p  = (lane >> 2) + pass * 8;
                int ch = lane & 3;
                uint4 v = *(const uint4*)(scr + p * 40 + ch * 8);
                int u = (nh * 4 + ch) ^ sw;
                *(uint4*)(dstb + (size_t)p * (B_MAX * 64) + u * 8) = v;
            }
        }
        __syncwarp();
    }
}

// ===========================================================================
// K2: fc GEMM M=128/block (grid 256), cp.async.bulk staging, 4 stages.
// smem: 4 stages x [A 16384 B | W 8192 B] = 98304; mbars @98304 (32 B);
//   QC @98368 (96), QS @98464 (96) -> 98560 B. 2 blocks/SM.
// Stage A: [128 m][64 halves] swizzled (u^(m&7)); W: [64 j][64] (u^(j&7)).
// Hf f32 [128][68] (34816 B) overlays stage area after GEMM.
// ===========================================================================
#define K2_SMEM  98560
#define K2_STG   24576   // bytes per stage
#define K2_WOFFB 16384   // byte offset of W within a stage
#define K2_TXB   24576u  // bytes per chunk (A 16K + W 8K)

__global__ __launch_bounds__(256, 2)
void k2_fc_head(const float* __restrict__ fcb,
                const float* __restrict__ prew, const float* __restrict__ preb,
                const float* __restrict__ qp,
                const float* __restrict__ postw, const float* __restrict__ postb,
                float* __restrict__ out)
{
    extern __shared__ __align__(128) unsigned char smraw[];
    float* QC = (float*)(smraw + 98368);
    float* QS = (float*)(smraw + 98464);
    float* Hf = (float*)smraw;

    const int tid  = threadIdx.x;
    const int wid  = tid >> 5;
    const int lane = tid & 31;
    const int qrow = lane >> 2;
    const int qc   = lane & 3;
    const int m0   = blockIdx.x * 128;
    const int mg   = wid & 3;
    const int ng   = wid >> 2;

    const unsigned mbar0 = s2u(smraw + 98304);

    if (tid == 0) {
        #pragma unroll
        for (int st = 0; st < 4; st++) mbar_init(mbar0 + st * 8, 1);
        asm volatile("fence.proxy.async.shared::cta;" ::: "memory");
    }
    if (tid >= 32 && tid < 56) {
        float s, cc;
        sincosf(qp[tid - 32] * 0.5f, &s, &cc);
        QC[tid - 32] = cc; QS[tid - 32] = s;
    }
    __syncthreads();

    auto issue = [&](int st, int ch) {
        unsigned mb = mbar0 + st * 8;
        mbar_expect_tx(mb, K2_TXB);
        bulk_g2s(s2u(smraw + st * K2_STG),
                 g_a2c + (size_t)ch * (B_MAX * 64) + (size_t)m0 * 64,
                 16384u, mb);
        bulk_g2s(s2u(smraw + st * K2_STG + K2_WOFFB),
                 g_fcw2 + ch * 4096, 8192u, mb);
    };

    if (tid == 0) { issue(0, 0); issue(1, 1); issue(2, 2); }

    float c[2][4][4] = {};

    #pragma unroll 1
    for (int ch = 0; ch < 16; ch++) {
        mbar_wait(mbar0 + (ch & 3) * 8, (ch >> 2) & 1);
        __syncthreads();     // all warps past mma(ch-1); buffer (ch+3)&3 free
        if (tid == 0 && ch + 3 < 16) issue((ch + 3) & 3, ch + 3);

        const __half* bufA = (const __half*)(smraw + (ch & 3) * K2_STG);
        const __half* bufW = (const __half*)(smraw + (ch & 3) * K2_STG + K2_WOFFB);
        #pragma unroll
        for (int ks = 0; ks < 4; ks++) {
            const int u0 = (((2 * ks)     ^ qrow) << 3) + 2 * qc;
            const int u1 = (((2 * ks + 1) ^ qrow) << 3) + 2 * qc;
            unsigned a[2][4];
            #pragma unroll
            for (int t = 0; t < 2; t++) {
                const __half* ap = bufA + (mg * 32 + t * 16 + qrow) * 64;
                a[t][0] = ldh2(ap + u0);        a[t][1] = ldh2(ap + 512 + u0);
                a[t][2] = ldh2(ap + u1);        a[t][3] = ldh2(ap + 512 + u1);
            }
            #pragma unroll
            for (int n = 0; n < 4; n++) {
                const __half* bp = bufW + (ng * 32 + n * 8 + qrow) * 64;
                unsigned b0 = ldh2(bp + u0), b1 = ldh2(bp + u1);
                mma_f16(c[0][n], a[0][0], a[0][1], a[0][2], a[0][3], b0, b1);
                mma_f16(c[1][n], a[1][0], a[1][1], a[1][2], a[1][3], b0, b1);
            }
        }
    }
    __syncthreads();    // all mma done; stage buffers dead -> Hf overlays

    // ---- bias + relu -> Hf -------------------------------------------------
    #pragma unroll
    for (int t = 0; t < 2; t++) {
        #pragma unroll
        for (int n = 0; n < 4; n++) {
            int j0 = ng * 32 + n * 8 + 2 * qc;
            int m  = mg * 32 + t * 16 + qrow;
            float b0 = __ldg(fcb + j0), b1 = __ldg(fcb + j0 + 1);
            *(float2*)(Hf + m * 68 + j0) =
                make_float2(fmaxf(c[t][n][0] + b0, 0.f), fmaxf(c[t][n][1] + b1, 0.f));
            *(float2*)(Hf + (m + 8) * 68 + j0) =
                make_float2(fmaxf(c[t][n][2] + b0, 0.f), fmaxf(c[t][n][3] + b1, 0.f));
        }
    }
    __syncthreads();

    // ---- quantum head: one thread per row (128 rows) -----------------------
    if (tid < 128) {
        const float* hrow = Hf + tid * 68;
        float4 acc = *(const float4*)preb;
        #pragma unroll
        for (int j4 = 0; j4 < 16; j4++) {
            float4 h4 = *(const float4*)(hrow + j4 * 4);
            float4 wa = __ldg((const float4*)prew + (j4 * 4 + 0));
            float4 wb = __ldg((const float4*)prew + (j4 * 4 + 1));
            float4 wc = __ldg((const float4*)prew + (j4 * 4 + 2));
            float4 wd = __ldg((const float4*)prew + (j4 * 4 + 3));
            acc.x = fmaf(h4.x, wa.x, acc.x); acc.y = fmaf(h4.x, wa.y, acc.y);
            acc.z = fmaf(h4.x, wa.z, acc.z); acc.w = fmaf(h4.x, wa.w, acc.w);
            acc.x = fmaf(h4.y, wb.x, acc.x); acc.y = fmaf(h4.y, wb.y, acc.y);
            acc.z = fmaf(h4.y, wb.z, acc.z); acc.w = fmaf(h4.y, wb.w, acc.w);
            acc.x = fmaf(h4.z, wc.x, acc.x); acc.y = fmaf(h4.z, wc.y, acc.y);
            acc.z = fmaf(h4.z, wc.z, acc.z); acc.w = fmaf(h4.z, wc.w, acc.w);
            acc.x = fmaf(h4.w, wd.x, acc.x); acc.y = fmaf(h4.w, wd.y, acc.y);
            acc.z = fmaf(h4.w, wd.z, acc.z); acc.w = fmaf(h4.w, wd.w, acc.w);
        }
        const float PI_2 = 1.57079632679489662f;
        float th[4] = { tanhf(acc.x) * PI_2, tanhf(acc.y) * PI_2,
                        tanhf(acc.z) * PI_2, tanhf(acc.w) * PI_2 };

        float st[16];
        #pragma unroll
        for (int i = 0; i < 16; i++) st[i] = 0.25f;

        #pragma unroll
        for (int w = 0; w < 4; w++) {
            float s, cc;
            sincosf(th[w] * 0.5f, &s, &cc);
            const int m = 8 >> w;
            #pragma unroll
            for (int i = 0; i < 16; i++) {
                if (!(i & m)) {
                    int j = i | m;
                    float aa = st[i], bb = st[j];
                    st[i] = cc * aa - s * bb;
                    st[j] = s * aa + cc * bb;
                }
            }
        }
        #pragma unroll
        for (int k = 0; k < 6; k++) {
            #pragma unroll
            for (int i = 0; i < 16; i++)
                if ((i & 8) && !(i & 4)) { float tv = st[i]; st[i] = st[i|4]; st[i|4] = tv; }
            #pragma unroll
            for (int i = 0; i < 16; i++)
                if ((i & 2) && !(i & 1)) { float tv = st[i]; st[i] = st[i|1]; st[i|1] = tv; }
            #pragma unroll
            for (int i = 0; i < 16; i++)
                if ((i & 4) && !(i & 2)) { float tv = st[i]; st[i] = st[i|2]; st[i|2] = tv; }
            #pragma unroll
            for (int w = 0; w < 4; w++) {
                float cc = QC[k * 4 + w], s = QS[k * 4 + w];
                const int m = 8 >> w;
                #pragma unroll
                for (int i = 0; i < 16; i++) {
                    if (!(i & m)) {
                        int j = i | m;
                        float aa = st[i], bb = st[j];
                        st[i] = cc * aa - s * bb;
                        st[j] = s * aa + cc * bb;
                    }
                }
            }
        }
        float z0 = 0.f, z1 = 0.f, z2 = 0.f, z3 = 0.f;
        #pragma unroll
        for (int i = 0; i < 16; i++) {
            float p = st[i] * st[i];
            z0 += (i & 8) ? -p : p;
            z1 += (i & 4) ? -p : p;
            z2 += (i & 2) ? -p : p;
            z3 += (i & 1) ? -p : p;
        }
        float tacc = __ldg(postb);
        tacc = fmaf(z0, __ldg(postw + 0), tacc);
        tacc = fmaf(z1, __ldg(postw + 1), tacc);
        tacc = fmaf(z2, __ldg(postw + 2), tacc);
        tacc = fmaf(z3, __ldg(postw + 3), tacc);
        out[m0 + tid] = 1.f / (1.f + expf(-tacc));
    }
}

// ===========================================================================
extern "C" void kernel_launch(void* const* d_in, const int* in_sizes, int n_in,
                              void* d_out, int out_size)
{
    const float* x     = (const float*)d_in[0];
    const float* c1w   = (const float*)d_in[1];
    const float* c1b   = (const float*)d_in[2];
    const float* c2w   = (const float*)d_in[3];
    const float* c2b   = (const float*)d_in[4];
    const float* fcw   = (const float*)d_in[5];
    const float* fcb   = (const float*)d_in[6];
    const float* prew  = (const float*)d_in[7];
    const float* preb  = (const float*)d_in[8];
    const float* qp    = (const float*)d_in[9];
    const float* postw = (const float*)d_in[10];
    const float* postb = (const float*)d_in[11];

    const int B = in_sizes[0] / 64;

    cudaFuncSetAttribute(k1_conv, cudaFuncAttributeMaxDynamicSharedMemorySize, K1_SMEM);
    cudaFuncSetAttribute(k2_fc_head, cudaFuncAttributeMaxDynamicSharedMemorySize, K2_SMEM);

    k1_conv<<<B / 32, 256, K1_SMEM>>>(x, c1w, c1b, c2w, c2b, fcw);
    k2_fc_head<<<B / 128, 256, K2_SMEM>>>(fcb, prew, preb, qp, postw, postb,
                                          (float*)d_out);
}